// round 13
// baseline (speedup 1.0000x reference)
#include <cuda_runtime.h>
#include <cuda_bf16.h>
#include <math_constants.h>

// CRF neg-log-likelihood, GB300 sm_103a.
// 64 CTAs x 64 threads (2 warps). Consolidated best-of-session:
// - linear-space forward recursion, bf16 partition smem ping-pong (R3)
// - exp(feats) precomputed to dynamic smem as SPLATTED bf162 words (R10/R12)
// - mask fast path: no mask LDS / SEL / carry in the loop (R12)
// - all-bf16 epilogue: swap-add + HMUL2 + STS.U16 (R7)
// - 8 accumulators: HFMA2 depth 4 instead of 7
// - rescale by p_prev[0] every 4 steps (off-path RCP/LG2)

namespace {
constexpr int NTAG   = 50;
constexpr int TSTART = NTAG - 2;   // 48
constexpr int TSTOP  = NTAG - 1;   // 49
constexpr int BATCH  = 64;
constexpr int SEQ    = 512;
constexpr int NTHR   = 64;
constexpr int NPAIR  = 28;         // bf162 pairs (56 slots: 50 + 6 zero pad)
constexpr int SMEM_EF_WORDS = SEQ * NTAG;       // splatted bf162 exp(feats)
constexpr int SMEM_BYTES    = SMEM_EF_WORDS * 4;
}

__device__ float    g_partial[BATCH];
__device__ unsigned g_ticket = 0;

__device__ __forceinline__ float warpSumF(float v) {
#pragma unroll
    for (int o = 16; o > 0; o >>= 1) v += __shfl_xor_sync(0xffffffffu, v, o);
    return v;
}
__device__ __forceinline__ int warpSumI(int v) {
#pragma unroll
    for (int o = 16; o > 0; o >>= 1) v += __shfl_xor_sync(0xffffffffu, v, o);
    return v;
}
__device__ __forceinline__ __nv_bfloat162 asbf2(float f) {
    return *reinterpret_cast<__nv_bfloat162*>(&f);
}
__device__ __forceinline__ __nv_bfloat162 u2b(unsigned u) {
    return *reinterpret_cast<__nv_bfloat162*>(&u);
}
__device__ __forceinline__ unsigned b2u(__nv_bfloat162 b) {
    return *reinterpret_cast<unsigned*>(&b);
}
__device__ __forceinline__ unsigned swap16(unsigned a) {
    unsigned r; asm("prmt.b32 %0, %1, 0, 0x1032;" : "=r"(r) : "r"(a)); return r;
}

// GEMV core, 8 accumulators (depth 4). Returns pair whose halves sum to q_j.
// Also exports p0 (low bf16 of pair word 0) as fp32.
__device__ __forceinline__ __nv_bfloat162 gemv8(
    const __nv_bfloat162* __restrict__ src,
    const __nv_bfloat162 (&et2)[NPAIR],
    float& p0f)
{
    const float4* sp4 = (const float4*)src;
    float4 v0 = sp4[0];
    float4 v1 = sp4[1];
    float4 v2 = sp4[2];
    float4 v3 = sp4[3];
    float4 v4 = sp4[4];
    float4 v5 = sp4[5];
    float4 v6 = sp4[6];

    p0f = __uint_as_float(__float_as_uint(v0.x) << 16);

    __nv_bfloat162 z = __floats2bfloat162_rn(0.f, 0.f);
    __nv_bfloat162 a0 = z, a1 = z, a2 = z, a3 = z;
    __nv_bfloat162 a4 = z, a5 = z, a6 = z, a7 = z;

    a0 = __hfma2(asbf2(v0.x), et2[0],  a0);
    a1 = __hfma2(asbf2(v0.y), et2[1],  a1);
    a2 = __hfma2(asbf2(v0.z), et2[2],  a2);
    a3 = __hfma2(asbf2(v0.w), et2[3],  a3);
    a4 = __hfma2(asbf2(v1.x), et2[4],  a4);
    a5 = __hfma2(asbf2(v1.y), et2[5],  a5);
    a6 = __hfma2(asbf2(v1.z), et2[6],  a6);
    a7 = __hfma2(asbf2(v1.w), et2[7],  a7);
    a0 = __hfma2(asbf2(v2.x), et2[8],  a0);
    a1 = __hfma2(asbf2(v2.y), et2[9],  a1);
    a2 = __hfma2(asbf2(v2.z), et2[10], a2);
    a3 = __hfma2(asbf2(v2.w), et2[11], a3);
    a4 = __hfma2(asbf2(v3.x), et2[12], a4);
    a5 = __hfma2(asbf2(v3.y), et2[13], a5);
    a6 = __hfma2(asbf2(v3.z), et2[14], a6);
    a7 = __hfma2(asbf2(v3.w), et2[15], a7);
    a0 = __hfma2(asbf2(v4.x), et2[16], a0);
    a1 = __hfma2(asbf2(v4.y), et2[17], a1);
    a2 = __hfma2(asbf2(v4.z), et2[18], a2);
    a3 = __hfma2(asbf2(v4.w), et2[19], a3);
    a4 = __hfma2(asbf2(v5.x), et2[20], a4);
    a5 = __hfma2(asbf2(v5.y), et2[21], a5);
    a6 = __hfma2(asbf2(v5.z), et2[22], a6);
    a7 = __hfma2(asbf2(v5.w), et2[23], a7);
    a0 = __hfma2(asbf2(v6.x), et2[24], a0);
    a1 = __hfma2(asbf2(v6.y), et2[25], a1);
    a2 = __hfma2(asbf2(v6.z), et2[26], a2);
    a3 = __hfma2(asbf2(v6.w), et2[27], a3);

    a0 = __hadd2(a0, a4);
    a1 = __hadd2(a1, a5);
    a2 = __hadd2(a2, a6);
    a3 = __hadd2(a3, a7);
    a0 = __hadd2(a0, a1);
    a2 = __hadd2(a2, a3);
    return __hadd2(a0, a2);
}

// FAST step (mask==1): all-bf16 epilogue, no SEL/carry.
template <bool RESCALE>
__device__ __forceinline__ void step_fast(
    int t, int j, int jf, bool act,
    const __nv_bfloat162* __restrict__ src,
    __nv_bfloat162*       __restrict__ dst,
    const __nv_bfloat162 (&et2)[NPAIR],
    unsigned& efw, float& offset,
    const unsigned* __restrict__ s_ef)
{
    float p0f;
    __nv_bfloat162 s2 = gemv8(src, et2, p0f);
    float rp0 = 1.f;
    if (RESCALE) rp0 = __frcp_rn(p0f);

    // (q,q) = (x+y, y+x); * splatted ef
    s2 = __hadd2(s2, u2b(swap16(b2u(s2))));
    __nv_bfloat162 q2 = __hmul2(s2, u2b(efw));
    if (RESCALE) q2 = __hmul2(q2, __float2bfloat162_rn(rp0));

    if (act) ((__nv_bfloat16*)dst)[j] = __low2bfloat16(q2);   // STS.U16

    efw = s_ef[(t + 1) * NTAG + jf];     // off-path prefetch (splatted ef)
    if (RESCALE) offset += __logf(p0f);

    __syncthreads();
}

// GENERAL step: honors mask (carry previous).
template <bool RESCALE>
__device__ __forceinline__ void step_gen(
    int t, int j, int jf, bool act,
    const __nv_bfloat162* __restrict__ src,
    __nv_bfloat162*       __restrict__ dst,
    const __nv_bfloat162 (&et2)[NPAIR],
    unsigned& efw, unsigned& pju, float& offset, int& m,
    const unsigned* __restrict__ s_ef,
    const int*      __restrict__ s_mask)
{
    float p0f;
    __nv_bfloat162 s2 = gemv8(src, et2, p0f);
    float rp0 = 1.f;
    if (RESCALE) rp0 = __frcp_rn(p0f);

    s2 = __hadd2(s2, u2b(swap16(b2u(s2))));
    unsigned q2u = b2u(__hmul2(s2, u2b(efw)));
    q2u = m ? q2u : pju;
    if (RESCALE) q2u = b2u(__hmul2(u2b(q2u), __float2bfloat162_rn(rp0)));
    pju = q2u;

    if (act) ((__nv_bfloat16*)dst)[j] = __low2bfloat16(u2b(q2u));

    efw = s_ef[(t + 1) * NTAG + jf];
    m   = s_mask[t + 1];
    if (RESCALE) offset += __logf(p0f);

    __syncthreads();
}

__global__ void __launch_bounds__(NTHR, 1)
crf_kernel(const float* __restrict__ feats,
           const int*   __restrict__ mask,
           const int*   __restrict__ tags,
           const float* __restrict__ trans,
           float*       __restrict__ out)
{
    const int b    = blockIdx.x;
    const int j    = threadIdx.x;
    const int jf   = min(j, NTAG - 1);
    const int lane = j & 31;
    const int wid  = j >> 5;
    const bool act = (j < NTAG);

    extern __shared__ unsigned s_ef[];       // [SEQ][NTAG] splatted bf162 ef

    __shared__ __align__(16) __nv_bfloat162 spA[NPAIR];
    __shared__ __align__(16) __nv_bfloat162 spB[NPAIR];
    __shared__ float s_fwd;
    __shared__ float s_acc[2];
    __shared__ int   s_len[2];
    __shared__ int   s_mask[SEQ + 1];
    __shared__ int   s_ones[2];
    __shared__ bool  s_last;
    __shared__ float s_red2[2];

    const float* fb = feats + (long long)b * SEQ * NTAG;
    const int*   mb = mask  + b * SEQ;
    const int*   tb = tags  + b * SEQ;

    // ---- prologue: mask + all-ones count + splatted exp(feats) ----
    {
        int cnt = 0;
        for (int t = j; t < SEQ; t += NTHR) { int v = mb[t]; s_mask[t] = v; cnt += v; }
        cnt = warpSumI(cnt);
        if (lane == 0) s_ones[wid] = cnt;
        if (j == 0) s_mask[SEQ] = 0;
    }
    {
        const float4* f4 = (const float4*)fb;    // 6400 float4
#pragma unroll 4
        for (int idx = j; idx < SEQ * NTAG / 4; idx += NTHR) {
            float4 v = f4[idx];
            uint4 e;
            e.x = b2u(__float2bfloat162_rn(__expf(v.x)));
            e.y = b2u(__float2bfloat162_rn(__expf(v.y)));
            e.z = b2u(__float2bfloat162_rn(__expf(v.z)));
            e.w = b2u(__float2bfloat162_rn(__expf(v.w)));
            ((uint4*)s_ef)[idx] = e;
        }
    }

    // exp(transitions) column j (thread j owns next-tag j)
    __nv_bfloat162 et2[NPAIR];
#pragma unroll
    for (int k = 0; k < NPAIR; k++) et2[k] = __floats2bfloat162_rn(0.f, 0.f);
    if (act) {
#pragma unroll
        for (int k = 0; k < 25; k++) {
            float e0 = __expf(trans[(2 * k)     * NTAG + j]);
            float e1 = __expf(trans[(2 * k + 1) * NTAG + j]);
            et2[k] = __floats2bfloat162_rn(e0, e1);
        }
    }

    // t = 0: normalize by partition0[tag 0]
    const float off0   = fb[0] + trans[TSTART * NTAG + 0];
    float       offset = off0;
    float p0 = act ? __expf(fb[j] + trans[TSTART * NTAG + j] - off0) : 0.f;
    unsigned pju = b2u(__float2bfloat162_rn(p0));
    if (j < 2 * NPAIR) {
        ((__nv_bfloat16*)spA)[j] = __low2bfloat16(u2b(pju));
        ((__nv_bfloat16*)spB)[j] = __float2bfloat16(0.f);   // zero pads once
    }
    __syncthreads();

    const bool allOnes = (s_ones[0] + s_ones[1]) == SEQ;
    unsigned efw = s_ef[1 * NTAG + jf];

    if (allOnes) {
        for (int t = 1; t + 3 < SEQ; t += 4) {
            step_fast<false>(t,     j, jf, act, spA, spB, et2, efw, offset, s_ef);
            step_fast<false>(t + 1, j, jf, act, spB, spA, et2, efw, offset, s_ef);
            step_fast<false>(t + 2, j, jf, act, spA, spB, et2, efw, offset, s_ef);
            step_fast<true >(t + 3, j, jf, act, spB, spA, et2, efw, offset, s_ef);
        }
        step_fast<false>(SEQ - 3, j, jf, act, spA, spB, et2, efw, offset, s_ef);
        step_fast<false>(SEQ - 2, j, jf, act, spB, spA, et2, efw, offset, s_ef);
        {   // final step inline (no prefetch)
            float p0f;
            __nv_bfloat162 s2 = gemv8(spA, et2, p0f);
            s2 = __hadd2(s2, u2b(swap16(b2u(s2))));
            __nv_bfloat162 q2 = __hmul2(s2, u2b(efw));
            if (act) ((__nv_bfloat16*)spB)[j] = __low2bfloat16(q2);
            __syncthreads();
        }
    } else {
        int m = s_mask[1];
        for (int t = 1; t + 3 < SEQ; t += 4) {
            step_gen<false>(t,     j, jf, act, spA, spB, et2, efw, pju, offset, m, s_ef, s_mask);
            step_gen<false>(t + 1, j, jf, act, spB, spA, et2, efw, pju, offset, m, s_ef, s_mask);
            step_gen<false>(t + 2, j, jf, act, spA, spB, et2, efw, pju, offset, m, s_ef, s_mask);
            step_gen<true >(t + 3, j, jf, act, spB, spA, et2, efw, pju, offset, m, s_ef, s_mask);
        }
        step_gen<false>(SEQ - 3, j, jf, act, spA, spB, et2, efw, pju, offset, m, s_ef, s_mask);
        step_gen<false>(SEQ - 2, j, jf, act, spB, spA, et2, efw, pju, offset, m, s_ef, s_mask);
        {
            float p0f;
            __nv_bfloat162 s2 = gemv8(spA, et2, p0f);
            s2 = __hadd2(s2, u2b(swap16(b2u(s2))));
            unsigned q2u = b2u(__hmul2(s2, u2b(efw)));
            q2u = m ? q2u : pju;
            if (act) ((__nv_bfloat16*)spB)[j] = __low2bfloat16(u2b(q2u));
            __syncthreads();
        }
    }

    // terminal (fp32, once): forward = log( sum_i p[i]*exp(trans[i,STOP]) ) + offset
    if (j == TSTOP) {
        float p0f;
        __nv_bfloat162 s2 = gemv8(spB, et2, p0f);
        float2 sf = __bfloat1622float2(s2);
        s_fwd = __logf(sf.x + sf.y) + offset;
    }

    // ---- gold score ----
    float acc = 0.f;
    int   len = 0;
#pragma unroll
    for (int t = j; t < SEQ; t += NTHR) {
        int tag  = tb[t];
        int prev = (t == 0) ? TSTART : tb[t - 1];
        int mm   = s_mask[t];
        if (mm) acc += fb[t * NTAG + tag] + trans[prev * NTAG + tag];
        len += mm;
    }
    acc = warpSumF(acc);
    len = warpSumI(len);
    if (lane == 0) { s_acc[wid] = acc; s_len[wid] = len; }
    __syncthreads();

    if (j == 0) {
        int   L     = s_len[0] + s_len[1];
        int   endid = tb[L - 1];
        float gold  = s_acc[0] + s_acc[1] + trans[endid * NTAG + TSTOP];
        g_partial[b] = s_fwd - gold;
        __threadfence();
        unsigned tk = atomicAdd(&g_ticket, 1u);
        s_last = (tk == BATCH - 1);
    }
    __syncthreads();

    if (s_last) {
        float v = ((volatile float*)g_partial)[j];
        v = warpSumF(v);
        if (lane == 0) s_red2[wid] = v;
        __syncthreads();
        if (j == 0) {
            out[0] = s_red2[0] + s_red2[1];
            g_ticket = 0;
        }
    }
}

extern "C" void kernel_launch(void* const* d_in, const int* in_sizes, int n_in,
                              void* d_out, int out_size)
{
    const float* feats = (const float*)d_in[0];
    const int*   mask  = (const int*)d_in[1];
    const int*   tags  = (const int*)d_in[2];
    const float* trans = (const float*)d_in[3];
    float* out = (float*)d_out;

    cudaFuncSetAttribute(crf_kernel,
                         cudaFuncAttributeMaxDynamicSharedMemorySize, SMEM_BYTES);
    crf_kernel<<<BATCH, NTHR, SMEM_BYTES>>>(feats, mask, tags, trans, out);
}

// round 14
// speedup vs baseline: 1.0348x; 1.0348x over previous
#include <cuda_runtime.h>
#include <cuda_bf16.h>
#include <math_constants.h>

// CRF neg-log-likelihood, GB300 sm_103a.
// 64 CTAs x 64 threads (2 warps). Consolidated minimal loop:
// - linear-space forward recursion, bf16 partition smem ping-pong
// - partition buffer EXACTLY 25 u32 (50 bf16): 6 LDS.128 + 1 LDS.32, 25 HFMA2
// - exp(feats) precomputed to dynamic smem as SPLATTED bf162 words
// - mask fast path (no mask LDS / SEL / carry in the loop)
// - all-bf16 epilogue: swap-add + HMUL2 + STS.U16
// - rescale by p_prev[0] every 4 steps (off-path RCP/LG2)

namespace {
constexpr int NTAG   = 50;
constexpr int TSTART = NTAG - 2;   // 48
constexpr int TSTOP  = NTAG - 1;   // 49
constexpr int BATCH  = 64;
constexpr int SEQ    = 512;
constexpr int NTHR   = 64;
constexpr int NPW    = 25;         // partition pair-words (exact, no pads)
constexpr int SMEM_EF_WORDS = SEQ * NTAG;       // splatted bf162 exp(feats)
constexpr int SMEM_BYTES    = SMEM_EF_WORDS * 4;
}

__device__ float    g_partial[BATCH];
__device__ unsigned g_ticket = 0;

__device__ __forceinline__ float warpSumF(float v) {
#pragma unroll
    for (int o = 16; o > 0; o >>= 1) v += __shfl_xor_sync(0xffffffffu, v, o);
    return v;
}
__device__ __forceinline__ int warpSumI(int v) {
#pragma unroll
    for (int o = 16; o > 0; o >>= 1) v += __shfl_xor_sync(0xffffffffu, v, o);
    return v;
}
__device__ __forceinline__ __nv_bfloat162 asbf2(float f) {
    return *reinterpret_cast<__nv_bfloat162*>(&f);
}
__device__ __forceinline__ __nv_bfloat162 u2b(unsigned u) {
    return *reinterpret_cast<__nv_bfloat162*>(&u);
}
__device__ __forceinline__ unsigned b2u(__nv_bfloat162 b) {
    return *reinterpret_cast<unsigned*>(&b);
}
__device__ __forceinline__ unsigned swap16(unsigned a) {
    unsigned r; asm("prmt.b32 %0, %1, 0, 0x1032;" : "=r"(r) : "r"(a)); return r;
}

// GEMV core: 6 LDS.128 + 1 LDS.32, 25 HFMA2 into 8 accumulators (depth 4),
// 7-HADD2 tree. Returns pair whose halves sum to q_j; exports p0 as fp32.
__device__ __forceinline__ __nv_bfloat162 gemv25(
    const unsigned* __restrict__ src,
    const __nv_bfloat162 (&et2)[NPW],
    float& p0f)
{
    const float4* sp4 = (const float4*)src;
    float4 v0 = sp4[0];
    float4 v1 = sp4[1];
    float4 v2 = sp4[2];
    float4 v3 = sp4[3];
    float4 v4 = sp4[4];
    float4 v5 = sp4[5];
    unsigned w24 = src[24];

    p0f = __uint_as_float(__float_as_uint(v0.x) << 16);

    __nv_bfloat162 z = __floats2bfloat162_rn(0.f, 0.f);
    __nv_bfloat162 a0 = z, a1 = z, a2 = z, a3 = z;
    __nv_bfloat162 a4 = z, a5 = z, a6 = z, a7 = z;

    a0 = __hfma2(asbf2(v0.x), et2[0],  a0);
    a1 = __hfma2(asbf2(v0.y), et2[1],  a1);
    a2 = __hfma2(asbf2(v0.z), et2[2],  a2);
    a3 = __hfma2(asbf2(v0.w), et2[3],  a3);
    a4 = __hfma2(asbf2(v1.x), et2[4],  a4);
    a5 = __hfma2(asbf2(v1.y), et2[5],  a5);
    a6 = __hfma2(asbf2(v1.z), et2[6],  a6);
    a7 = __hfma2(asbf2(v1.w), et2[7],  a7);
    a0 = __hfma2(asbf2(v2.x), et2[8],  a0);
    a1 = __hfma2(asbf2(v2.y), et2[9],  a1);
    a2 = __hfma2(asbf2(v2.z), et2[10], a2);
    a3 = __hfma2(asbf2(v2.w), et2[11], a3);
    a4 = __hfma2(asbf2(v3.x), et2[12], a4);
    a5 = __hfma2(asbf2(v3.y), et2[13], a5);
    a6 = __hfma2(asbf2(v3.z), et2[14], a6);
    a7 = __hfma2(asbf2(v3.w), et2[15], a7);
    a0 = __hfma2(asbf2(v4.x), et2[16], a0);
    a1 = __hfma2(asbf2(v4.y), et2[17], a1);
    a2 = __hfma2(asbf2(v4.z), et2[18], a2);
    a3 = __hfma2(asbf2(v4.w), et2[19], a3);
    a4 = __hfma2(asbf2(v5.x), et2[20], a4);
    a5 = __hfma2(asbf2(v5.y), et2[21], a5);
    a6 = __hfma2(asbf2(v5.z), et2[22], a6);
    a7 = __hfma2(asbf2(v5.w), et2[23], a7);
    a0 = __hfma2(u2b(w24),    et2[24], a0);

    a0 = __hadd2(a0, a4);
    a1 = __hadd2(a1, a5);
    a2 = __hadd2(a2, a6);
    a3 = __hadd2(a3, a7);
    a0 = __hadd2(a0, a1);
    a2 = __hadd2(a2, a3);
    return __hadd2(a0, a2);
}

// FAST step (mask==1): all-bf16 epilogue, no SEL/carry.
template <bool RESCALE>
__device__ __forceinline__ void step_fast(
    int t, int j, int jf, bool act,
    const unsigned* __restrict__ src,
    unsigned*       __restrict__ dst,
    const __nv_bfloat162 (&et2)[NPW],
    unsigned& efw, float& offset,
    const unsigned* __restrict__ s_ef)
{
    float p0f;
    __nv_bfloat162 s2 = gemv25(src, et2, p0f);
    float rp0 = 1.f;
    if (RESCALE) rp0 = __frcp_rn(p0f);

    s2 = __hadd2(s2, u2b(swap16(b2u(s2))));      // (x+y) in both halves
    __nv_bfloat162 q2 = __hmul2(s2, u2b(efw));   // * splatted ef
    if (RESCALE) q2 = __hmul2(q2, __float2bfloat162_rn(rp0));

    if (act) ((__nv_bfloat16*)dst)[j] = __low2bfloat16(q2);   // STS.U16

    efw = s_ef[(t + 1) * NTAG + jf];             // off-path prefetch
    if (RESCALE) offset += __logf(p0f);

    __syncthreads();
}

// GENERAL step: honors mask (carry previous).
template <bool RESCALE>
__device__ __forceinline__ void step_gen(
    int t, int j, int jf, bool act,
    const unsigned* __restrict__ src,
    unsigned*       __restrict__ dst,
    const __nv_bfloat162 (&et2)[NPW],
    unsigned& efw, unsigned& pju, float& offset, int& m,
    const unsigned* __restrict__ s_ef,
    const int*      __restrict__ s_mask)
{
    float p0f;
    __nv_bfloat162 s2 = gemv25(src, et2, p0f);
    float rp0 = 1.f;
    if (RESCALE) rp0 = __frcp_rn(p0f);

    s2 = __hadd2(s2, u2b(swap16(b2u(s2))));
    unsigned q2u = b2u(__hmul2(s2, u2b(efw)));
    q2u = m ? q2u : pju;
    if (RESCALE) q2u = b2u(__hmul2(u2b(q2u), __float2bfloat162_rn(rp0)));
    pju = q2u;

    if (act) ((__nv_bfloat16*)dst)[j] = __low2bfloat16(u2b(q2u));

    efw = s_ef[(t + 1) * NTAG + jf];
    m   = s_mask[t + 1];
    if (RESCALE) offset += __logf(p0f);

    __syncthreads();
}

__global__ void __launch_bounds__(NTHR, 1)
crf_kernel(const float* __restrict__ feats,
           const int*   __restrict__ mask,
           const int*   __restrict__ tags,
           const float* __restrict__ trans,
           float*       __restrict__ out)
{
    const int b    = blockIdx.x;
    const int j    = threadIdx.x;
    const int jf   = min(j, NTAG - 1);
    const int lane = j & 31;
    const int wid  = j >> 5;
    const bool act = (j < NTAG);

    extern __shared__ unsigned s_ef[];       // [SEQ][NTAG] splatted bf162 ef

    __shared__ __align__(16) unsigned spA[NPW + 1];
    __shared__ __align__(16) unsigned spB[NPW + 1];
    __shared__ float s_fwd;
    __shared__ float s_acc[2];
    __shared__ int   s_len[2];
    __shared__ int   s_mask[SEQ + 1];
    __shared__ int   s_ones[2];
    __shared__ bool  s_last;
    __shared__ float s_red2[2];

    const float* fb = feats + (long long)b * SEQ * NTAG;
    const int*   mb = mask  + b * SEQ;
    const int*   tb = tags  + b * SEQ;

    // ---- prologue: mask + all-ones count + splatted exp(feats) ----
    {
        int cnt = 0;
        for (int t = j; t < SEQ; t += NTHR) { int v = mb[t]; s_mask[t] = v; cnt += v; }
        cnt = warpSumI(cnt);
        if (lane == 0) s_ones[wid] = cnt;
        if (j == 0) s_mask[SEQ] = 0;
    }
    {
        const float4* f4 = (const float4*)fb;    // 6400 float4
#pragma unroll 4
        for (int idx = j; idx < SEQ * NTAG / 4; idx += NTHR) {
            float4 v = f4[idx];
            uint4 e;
            e.x = b2u(__float2bfloat162_rn(__expf(v.x)));
            e.y = b2u(__float2bfloat162_rn(__expf(v.y)));
            e.z = b2u(__float2bfloat162_rn(__expf(v.z)));
            e.w = b2u(__float2bfloat162_rn(__expf(v.w)));
            ((uint4*)s_ef)[idx] = e;
        }
    }

    // exp(transitions) column j (thread j owns next-tag j):
    // et2[k] = (e^T[2k][j], e^T[2k+1][j])
    __nv_bfloat162 et2[NPW];
    if (act) {
#pragma unroll
        for (int k = 0; k < NPW; k++) {
            float e0 = __expf(trans[(2 * k)     * NTAG + j]);
            float e1 = __expf(trans[(2 * k + 1) * NTAG + j]);
            et2[k] = __floats2bfloat162_rn(e0, e1);
        }
    } else {
#pragma unroll
        for (int k = 0; k < NPW; k++) et2[k] = __floats2bfloat162_rn(0.f, 0.f);
    }

    // t = 0: normalize by partition0[tag 0]
    const float off0   = fb[0] + trans[TSTART * NTAG + 0];
    float       offset = off0;
    float p0 = act ? __expf(fb[j] + trans[TSTART * NTAG + j] - off0) : 0.f;
    unsigned pju = b2u(__float2bfloat162_rn(p0));
    if (act) ((__nv_bfloat16*)spA)[j] = __low2bfloat16(u2b(pju));
    __syncthreads();

    const bool allOnes = (s_ones[0] + s_ones[1]) == SEQ;
    unsigned efw = s_ef[1 * NTAG + jf];

    if (allOnes) {
        for (int t = 1; t + 3 < SEQ; t += 4) {
            step_fast<false>(t,     j, jf, act, spA, spB, et2, efw, offset, s_ef);
            step_fast<false>(t + 1, j, jf, act, spB, spA, et2, efw, offset, s_ef);
            step_fast<false>(t + 2, j, jf, act, spA, spB, et2, efw, offset, s_ef);
            step_fast<true >(t + 3, j, jf, act, spB, spA, et2, efw, offset, s_ef);
        }
        step_fast<false>(SEQ - 3, j, jf, act, spA, spB, et2, efw, offset, s_ef);
        step_fast<false>(SEQ - 2, j, jf, act, spB, spA, et2, efw, offset, s_ef);
        {   // final step inline (no prefetch)
            float p0f;
            __nv_bfloat162 s2 = gemv25(spA, et2, p0f);
            s2 = __hadd2(s2, u2b(swap16(b2u(s2))));
            __nv_bfloat162 q2 = __hmul2(s2, u2b(efw));
            if (act) ((__nv_bfloat16*)spB)[j] = __low2bfloat16(q2);
            __syncthreads();
        }
    } else {
        int m = s_mask[1];
        for (int t = 1; t + 3 < SEQ; t += 4) {
            step_gen<false>(t,     j, jf, act, spA, spB, et2, efw, pju, offset, m, s_ef, s_mask);
            step_gen<false>(t + 1, j, jf, act, spB, spA, et2, efw, pju, offset, m, s_ef, s_mask);
            step_gen<false>(t + 2, j, jf, act, spA, spB, et2, efw, pju, offset, m, s_ef, s_mask);
            step_gen<true >(t + 3, j, jf, act, spB, spA, et2, efw, pju, offset, m, s_ef, s_mask);
        }
        step_gen<false>(SEQ - 3, j, jf, act, spA, spB, et2, efw, pju, offset, m, s_ef, s_mask);
        step_gen<false>(SEQ - 2, j, jf, act, spB, spA, et2, efw, pju, offset, m, s_ef, s_mask);
        {
            float p0f;
            __nv_bfloat162 s2 = gemv25(spA, et2, p0f);
            s2 = __hadd2(s2, u2b(swap16(b2u(s2))));
            unsigned q2u = b2u(__hmul2(s2, u2b(efw)));
            q2u = m ? q2u : pju;
            if (act) ((__nv_bfloat16*)spB)[j] = __low2bfloat16(u2b(q2u));
            __syncthreads();
        }
    }

    // terminal (fp32, once): forward = log( sum_i p[i]*exp(trans[i,STOP]) ) + offset
    if (j == TSTOP) {
        float p0f;
        __nv_bfloat162 s2 = gemv25(spB, et2, p0f);
        float2 sf = __bfloat1622float2(s2);
        s_fwd = __logf(sf.x + sf.y) + offset;
    }

    // ---- gold score ----
    float acc = 0.f;
    int   len = 0;
#pragma unroll
    for (int t = j; t < SEQ; t += NTHR) {
        int tag  = tb[t];
        int prev = (t == 0) ? TSTART : tb[t - 1];
        int mm   = s_mask[t];
        if (mm) acc += fb[t * NTAG + tag] + trans[prev * NTAG + tag];
        len += mm;
    }
    acc = warpSumF(acc);
    len = warpSumI(len);
    if (lane == 0) { s_acc[wid] = acc; s_len[wid] = len; }
    __syncthreads();

    if (j == 0) {
        int   L     = s_len[0] + s_len[1];
        int   endid = tb[L - 1];
        float gold  = s_acc[0] + s_acc[1] + trans[endid * NTAG + TSTOP];
        g_partial[b] = s_fwd - gold;
        __threadfence();
        unsigned tk = atomicAdd(&g_ticket, 1u);
        s_last = (tk == BATCH - 1);
    }
    __syncthreads();

    if (s_last) {
        float v = ((volatile float*)g_partial)[j];
        v = warpSumF(v);
        if (lane == 0) s_red2[wid] = v;
        __syncthreads();
        if (j == 0) {
            out[0] = s_red2[0] + s_red2[1];
            g_ticket = 0;
        }
    }
}

extern "C" void kernel_launch(void* const* d_in, const int* in_sizes, int n_in,
                              void* d_out, int out_size)
{
    const float* feats = (const float*)d_in[0];
    const int*   mask  = (const int*)d_in[1];
    const int*   tags  = (const int*)d_in[2];
    const float* trans = (const float*)d_in[3];
    float* out = (float*)d_out;

    cudaFuncSetAttribute(crf_kernel,
                         cudaFuncAttributeMaxDynamicSharedMemorySize, SMEM_BYTES);
    crf_kernel<<<BATCH, NTHR, SMEM_BYTES>>>(feats, mask, tags, trans, out);
}